// round 6
// baseline (speedup 1.0000x reference)
#include <cuda_runtime.h>

#define N_NODES 50000
#define N_EDGES 800000
#define IN_DIM 64
#define HID_DIM 128
#define OUT_DIM 40
#define NB_SCAN 49   // ceil(50000/1024)
#define HL_STRIDE 64 // padded row stride for g_hl (256B aligned)

// ---------------- scratch (device globals; no allocation) ----------------
__device__ int   g_cnt[N_NODES];
__device__ int   g_rowptr[N_NODES + 1];
__device__ int   g_cursor[N_NODES];
__device__ int   g_col[N_EDGES];
__device__ int   g_bsum[NB_SCAN];
__device__ float g_hl[N_NODES * HL_STRIDE]; // h @ Wl2^T (pre-aggregation), padded rows
__device__ float g_hr[N_NODES * OUT_DIM];   // h @ Wr2^T

// ---------------- packed f32x2 helpers ----------------
__device__ __forceinline__ unsigned long long pack2(float v) {
    unsigned long long r;
    asm("mov.b64 %0, {%1, %1};" : "=l"(r) : "f"(v));
    return r;
}
__device__ __forceinline__ void ffma2(unsigned long long& d,
                                      unsigned long long a,
                                      unsigned long long b) {
    asm("fma.rn.f32x2 %0, %1, %2, %0;" : "+l"(d) : "l"(a), "l"(b));
}
__device__ __forceinline__ float2 unpack2(unsigned long long v) {
    float2 r;
    asm("mov.b64 {%0, %1}, %2;" : "=f"(r.x), "=f"(r.y) : "l"(v));
    return r;
}

// ---------------- CSR build ----------------
__global__ void k_zero_cnt() {
    int i = blockIdx.x * blockDim.x + threadIdx.x;
    if (i < N_NODES) g_cnt[i] = 0;
}

// 4 edges per thread (N_EDGES divisible by 4; dst base 3.2MB offset keeps 16B align)
__global__ void k_degree(const int* __restrict__ ei) {
    int i = blockIdx.x * blockDim.x + threadIdx.x;
    if (i < N_EDGES / 4) {
        int4 d = ((const int4*)(ei + N_EDGES))[i];
        atomicAdd(&g_cnt[d.x], 1);
        atomicAdd(&g_cnt[d.y], 1);
        atomicAdd(&g_cnt[d.z], 1);
        atomicAdd(&g_cnt[d.w], 1);
    }
}

// phase 1: per-block (1024 elems) exclusive scan; block totals to g_bsum
__global__ void __launch_bounds__(1024) k_scan_part() {
    __shared__ int wsum[32];
    int tid = threadIdx.x, lane = tid & 31, warp = tid >> 5;
    int i = blockIdx.x * 1024 + tid;
    int v = (i < N_NODES) ? g_cnt[i] : 0;
    int xs = v;
    #pragma unroll
    for (int off = 1; off < 32; off <<= 1) {
        int t = __shfl_up_sync(0xffffffffu, xs, off);
        if (lane >= off) xs += t;
    }
    if (lane == 31) wsum[warp] = xs;
    __syncthreads();
    if (warp == 0) {
        int s = wsum[lane];
        #pragma unroll
        for (int off = 1; off < 32; off <<= 1) {
            int t = __shfl_up_sync(0xffffffffu, s, off);
            if (lane >= off) s += t;
        }
        wsum[lane] = s;
    }
    __syncthreads();
    int woff = (warp > 0) ? wsum[warp - 1] : 0;
    if (i < N_NODES) g_rowptr[i] = woff + xs - v;   // local exclusive
    if (tid == 1023) g_bsum[blockIdx.x] = woff + xs;
}

// phase 2: add block offsets (warp-0 shfl-scans the 49 totals into smem)
__global__ void __launch_bounds__(256) k_scan_add() {
    __shared__ int sp[64];            // exclusive prefix of block sums
    __shared__ int s_tot;
    int tid = threadIdx.x;
    if (tid < 32) {
        int lane = tid;
        int v0 = (lane < NB_SCAN) ? g_bsum[lane] : 0;
        int v1 = (32 + lane < NB_SCAN) ? g_bsum[32 + lane] : 0;
        int p0 = v0;
        #pragma unroll
        for (int off = 1; off < 32; off <<= 1) {
            int t = __shfl_up_sync(0xffffffffu, p0, off);
            if (lane >= off) p0 += t;
        }
        int tot0 = __shfl_sync(0xffffffffu, p0, 31);
        int p1 = v1;
        #pragma unroll
        for (int off = 1; off < 32; off <<= 1) {
            int t = __shfl_up_sync(0xffffffffu, p1, off);
            if (lane >= off) p1 += t;
        }
        sp[lane] = p0 - v0;
        sp[32 + lane] = tot0 + p1 - v1;
        if (lane == 31) s_tot = tot0 + p1;
    }
    __syncthreads();
    int i = blockIdx.x * 256 + tid;
    if (i < N_NODES) {
        int r = g_rowptr[i] + sp[i >> 10];
        g_rowptr[i] = r;
        g_cursor[i] = r;
    }
    if (i == 0) g_rowptr[N_NODES] = s_tot;
}

// 4 edges per thread
__global__ void k_fill(const int* __restrict__ ei) {
    int i = blockIdx.x * blockDim.x + threadIdx.x;
    if (i < N_EDGES / 4) {
        int4 s = ((const int4*)ei)[i];
        int4 d = ((const int4*)(ei + N_EDGES))[i];
        g_col[atomicAdd(&g_cursor[d.x], 1)] = s.x;
        g_col[atomicAdd(&g_cursor[d.y], 1)] = s.y;
        g_col[atomicAdd(&g_cursor[d.z], 1)] = s.z;
        g_col[atomicAdd(&g_cursor[d.w], 1)] = s.w;
    }
}

// ---------------- fused agg1 + layer-1 + layer-2 GEMM ----------------
// smem: s_dat[128][65] | s_w 16384 (packed weights / s_out) | s_b 128
#define G12_SMEM_FLOATS (128 * 65 + 16384 + 128)
__global__ void __launch_bounds__(256) k_gemm12(
    const float* __restrict__ x,
    const float* __restrict__ Wl1, const float* __restrict__ bl1,
    const float* __restrict__ Wr1,
    const float* __restrict__ Wl2, const float* __restrict__ Wr2)
{
    extern __shared__ float sm[];
    float* s_dat = sm;                   // 128*65: [k][node] inputs, then [o][node] h
    float* s_w   = sm + 128 * 65;        // 16384
    float* s_b   = s_w + 16384;          // 128
    int tid = threadIdx.x;
    int n0 = blockIdx.x * 64;
    int rem = min(64, N_NODES - n0);

    // layer-1 weights, FFMA2-packed: float idx = (o>>1)*128 + (k>>1)*4 + (k&1)*2 + (o&1)
    for (int idx = tid; idx < 8192; idx += 256) {
        int o = idx >> 6, k = idx & 63;
        int dst = ((o >> 1) << 7) + ((k >> 1) << 2) + ((k & 1) << 1) + (o & 1);
        s_w[dst] = Wl1[idx];
        s_w[8192 + dst] = Wr1[idx];
    }
    if (tid < 128) s_b[tid] = bl1[tid];

    // x rows (W_r input) -> s_dat[64..128)[node]
    for (int idx = tid; idx < 64 * 64; idx += 256) {
        int l2 = idx >> 6, k = idx & 63;
        float v = (l2 < rem) ? x[(n0 + l2) * 64 + k] : 0.f;
        s_dat[(64 + k) * 65 + l2] = v;
    }

    // neighbor mean of x -> s_dat[0..64)[node]   (warp per node, 8 nodes/warp, unroll 8)
    {
        int warp = tid >> 5, lane = tid & 31;
        const float2* xp = (const float2*)x;
        for (int wn = warp; wn < 64; wn += 8) {
            float2 acc = make_float2(0.f, 0.f);
            int deg = 0;
            if (wn < rem) {
                int node = n0 + wn;
                int s = g_rowptr[node], e = g_rowptr[node + 1];
                deg = e - s;
                for (int base = s; base < e; base += 32) {
                    int j = base + lane;
                    int myc = (j < e) ? g_col[j] : 0;
                    int cnt = min(32, e - base);
                    int jj = 0;
                    for (; jj + 8 <= cnt; jj += 8) {
                        int c0 = __shfl_sync(0xffffffffu, myc, jj);
                        int c1 = __shfl_sync(0xffffffffu, myc, jj + 1);
                        int c2 = __shfl_sync(0xffffffffu, myc, jj + 2);
                        int c3 = __shfl_sync(0xffffffffu, myc, jj + 3);
                        int c4 = __shfl_sync(0xffffffffu, myc, jj + 4);
                        int c5 = __shfl_sync(0xffffffffu, myc, jj + 5);
                        int c6 = __shfl_sync(0xffffffffu, myc, jj + 6);
                        int c7 = __shfl_sync(0xffffffffu, myc, jj + 7);
                        float2 v0 = xp[c0 * 32 + lane];
                        float2 v1 = xp[c1 * 32 + lane];
                        float2 v2 = xp[c2 * 32 + lane];
                        float2 v3 = xp[c3 * 32 + lane];
                        float2 v4 = xp[c4 * 32 + lane];
                        float2 v5 = xp[c5 * 32 + lane];
                        float2 v6 = xp[c6 * 32 + lane];
                        float2 v7 = xp[c7 * 32 + lane];
                        acc.x += ((v0.x + v1.x) + (v2.x + v3.x)) + ((v4.x + v5.x) + (v6.x + v7.x));
                        acc.y += ((v0.y + v1.y) + (v2.y + v3.y)) + ((v4.y + v5.y) + (v6.y + v7.y));
                    }
                    for (; jj + 4 <= cnt; jj += 4) {
                        int c0 = __shfl_sync(0xffffffffu, myc, jj);
                        int c1 = __shfl_sync(0xffffffffu, myc, jj + 1);
                        int c2 = __shfl_sync(0xffffffffu, myc, jj + 2);
                        int c3 = __shfl_sync(0xffffffffu, myc, jj + 3);
                        float2 v0 = xp[c0 * 32 + lane];
                        float2 v1 = xp[c1 * 32 + lane];
                        float2 v2 = xp[c2 * 32 + lane];
                        float2 v3 = xp[c3 * 32 + lane];
                        acc.x += (v0.x + v1.x) + (v2.x + v3.x);
                        acc.y += (v0.y + v1.y) + (v2.y + v3.y);
                    }
                    for (; jj < cnt; jj++) {
                        int c = __shfl_sync(0xffffffffu, myc, jj);
                        float2 v = xp[c * 32 + lane];
                        acc.x += v.x; acc.y += v.y;
                    }
                }
            }
            float inv = 1.0f / (float)max(deg, 1);
            s_dat[(2 * lane) * 65 + wn] = acc.x * inv;
            s_dat[(2 * lane + 1) * 65 + wn] = acc.y * inv;
        }
    }
    __syncthreads();

    // ---- layer 1: 128 outputs, K=64 dual weights, FFMA2 ----
    int l = tid & 63;
    int pbase = (tid >> 6) * 16;   // 16 output pairs -> outputs [32*wg, 32*wg+32)
    unsigned long long d1[16];
    #pragma unroll
    for (int p = 0; p < 16; p++) d1[p] = 0ull;
    {
        const ulonglong2* wl = (const ulonglong2*)s_w;            // [P*32 + kk]
        const ulonglong2* wr = (const ulonglong2*)(s_w + 8192);
        for (int kk = 0; kk < 32; kk++) {
            float m0 = s_dat[(2 * kk) * 65 + l];
            float m1 = s_dat[(2 * kk + 1) * 65 + l];
            float y0 = s_dat[(64 + 2 * kk) * 65 + l];
            float y1 = s_dat[(64 + 2 * kk + 1) * 65 + l];
            unsigned long long mm0 = pack2(m0), mm1 = pack2(m1);
            unsigned long long yy0 = pack2(y0), yy1 = pack2(y1);
            #pragma unroll
            for (int p = 0; p < 16; p++) {
                ulonglong2 a = wl[(pbase + p) * 32 + kk];
                ffma2(d1[p], a.x, mm0);
                ffma2(d1[p], a.y, mm1);
                ulonglong2 b = wr[(pbase + p) * 32 + kk];
                ffma2(d1[p], b.x, yy0);
                ffma2(d1[p], b.y, yy1);
            }
        }
    }
    __syncthreads();   // done reading s_dat inputs + layer-1 weights

    // h (+bias, relu) -> s_dat[o][node]  (o-major == k-major for layer 2)
    #pragma unroll
    for (int p = 0; p < 16; p++) {
        int o = 2 * (pbase + p);
        float2 v = unpack2(d1[p]);
        s_dat[o * 65 + l] = fmaxf(v.x + s_b[o], 0.f);
        s_dat[(o + 1) * 65 + l] = fmaxf(v.y + s_b[o + 1], 0.f);
    }
    // layer-2 weights (80 outputs: 40 Wl2 then 40 Wr2), FFMA2-packed
    for (int idx = tid; idx < 5120; idx += 256) {
        int o = idx >> 7, k = idx & 127;
        int dst = ((o >> 1) << 8) + ((k >> 1) << 2) + ((k & 1) << 1) + (o & 1);
        s_w[dst] = Wl2[idx];
        int o2 = o + 40;
        int dst2 = ((o2 >> 1) << 8) + ((k >> 1) << 2) + ((k & 1) << 1) + (o2 & 1);
        s_w[dst2] = Wr2[idx];
    }
    __syncthreads();

    // ---- layer 2: 80 outputs, K=128, FFMA2 ----
    int pbase2 = (tid >> 6) * 10;   // 10 pairs -> outputs [20*wg, 20*wg+20)
    unsigned long long d2[10];
    #pragma unroll
    for (int p = 0; p < 10; p++) d2[p] = 0ull;
    {
        const ulonglong2* w2 = (const ulonglong2*)s_w;    // [P*64 + kk]
        for (int kk = 0; kk < 64; kk++) {
            float h0 = s_dat[(2 * kk) * 65 + l];
            float h1 = s_dat[(2 * kk + 1) * 65 + l];
            unsigned long long hh0 = pack2(h0), hh1 = pack2(h1);
            #pragma unroll
            for (int p = 0; p < 10; p++) {
                ulonglong2 a = w2[(pbase2 + p) * 64 + kk];
                ffma2(d2[p], a.x, hh0);
                ffma2(d2[p], a.y, hh1);
            }
        }
    }
    // stage at s_w+10240 (80*65=5200 <= 6144 free) for coalesced writes
    float* s_out = s_w + 10240;
    #pragma unroll
    for (int p = 0; p < 10; p++) {
        int o = 2 * (pbase2 + p);
        float2 v = unpack2(d2[p]);
        s_out[o * 65 + l] = v.x;
        s_out[(o + 1) * 65 + l] = v.y;
    }
    __syncthreads();
    for (int idx = tid; idx < rem * 40; idx += 256) {
        int n = idx / 40, o = idx % 40;
        g_hl[(n0 + n) * HL_STRIDE + o] = s_out[o * 65 + n];
        g_hr[(n0 + n) * 40 + o] = s_out[(40 + o) * 65 + n];
    }
}

// ---------------- fused layer-2 aggregation + epilogue (unroll 8) ----------------
__global__ void k_agglout(const float* __restrict__ bl, float* __restrict__ out) {
    int node = (blockIdx.x * blockDim.x + threadIdx.x) >> 5;
    int lane = threadIdx.x & 31;
    if (node >= N_NODES) return;
    int s = g_rowptr[node], e = g_rowptr[node + 1];
    float acc0 = 0.f, acc1 = 0.f;
    for (int base = s; base < e; base += 32) {
        int j = base + lane;
        int myc = (j < e) ? g_col[j] : 0;
        int cnt = min(32, e - base);
        int jj = 0;
        for (; jj + 8 <= cnt; jj += 8) {
            int c0 = __shfl_sync(0xffffffffu, myc, jj);
            int c1 = __shfl_sync(0xffffffffu, myc, jj + 1);
            int c2 = __shfl_sync(0xffffffffu, myc, jj + 2);
            int c3 = __shfl_sync(0xffffffffu, myc, jj + 3);
            int c4 = __shfl_sync(0xffffffffu, myc, jj + 4);
            int c5 = __shfl_sync(0xffffffffu, myc, jj + 5);
            int c6 = __shfl_sync(0xffffffffu, myc, jj + 6);
            int c7 = __shfl_sync(0xffffffffu, myc, jj + 7);
            float a0 = g_hl[c0 * HL_STRIDE + lane];
            float a1 = g_hl[c1 * HL_STRIDE + lane];
            float a2 = g_hl[c2 * HL_STRIDE + lane];
            float a3 = g_hl[c3 * HL_STRIDE + lane];
            float a4 = g_hl[c4 * HL_STRIDE + lane];
            float a5 = g_hl[c5 * HL_STRIDE + lane];
            float a6 = g_hl[c6 * HL_STRIDE + lane];
            float a7 = g_hl[c7 * HL_STRIDE + lane];
            acc0 += ((a0 + a1) + (a2 + a3)) + ((a4 + a5) + (a6 + a7));
            if (lane < 8) {
                float b0 = g_hl[c0 * HL_STRIDE + 32 + lane];
                float b1 = g_hl[c1 * HL_STRIDE + 32 + lane];
                float b2 = g_hl[c2 * HL_STRIDE + 32 + lane];
                float b3 = g_hl[c3 * HL_STRIDE + 32 + lane];
                float b4 = g_hl[c4 * HL_STRIDE + 32 + lane];
                float b5 = g_hl[c5 * HL_STRIDE + 32 + lane];
                float b6 = g_hl[c6 * HL_STRIDE + 32 + lane];
                float b7 = g_hl[c7 * HL_STRIDE + 32 + lane];
                acc1 += ((b0 + b1) + (b2 + b3)) + ((b4 + b5) + (b6 + b7));
            }
        }
        for (; jj + 4 <= cnt; jj += 4) {
            int c0 = __shfl_sync(0xffffffffu, myc, jj);
            int c1 = __shfl_sync(0xffffffffu, myc, jj + 1);
            int c2 = __shfl_sync(0xffffffffu, myc, jj + 2);
            int c3 = __shfl_sync(0xffffffffu, myc, jj + 3);
            float a0 = g_hl[c0 * HL_STRIDE + lane];
            float a1 = g_hl[c1 * HL_STRIDE + lane];
            float a2 = g_hl[c2 * HL_STRIDE + lane];
            float a3 = g_hl[c3 * HL_STRIDE + lane];
            acc0 += (a0 + a1) + (a2 + a3);
            if (lane < 8) {
                float b0 = g_hl[c0 * HL_STRIDE + 32 + lane];
                float b1 = g_hl[c1 * HL_STRIDE + 32 + lane];
                float b2 = g_hl[c2 * HL_STRIDE + 32 + lane];
                float b3 = g_hl[c3 * HL_STRIDE + 32 + lane];
                acc1 += (b0 + b1) + (b2 + b3);
            }
        }
        for (; jj < cnt; jj++) {
            int c = __shfl_sync(0xffffffffu, myc, jj);
            acc0 += g_hl[c * HL_STRIDE + lane];
            if (lane < 8) acc1 += g_hl[c * HL_STRIDE + 32 + lane];
        }
    }
    float inv = 1.0f / (float)max(e - s, 1);
    float v0 = fmaxf(acc0 * inv + g_hr[node * 40 + lane] + bl[lane], 0.f);
    float v1 = 0.f;
    if (lane < 8)
        v1 = fmaxf(acc1 * inv + g_hr[node * 40 + 32 + lane] + bl[32 + lane], 0.f);
    float m = fmaxf(v0, (lane < 8) ? v1 : -1e30f);
    #pragma unroll
    for (int off = 16; off > 0; off >>= 1)
        m = fmaxf(m, __shfl_xor_sync(0xffffffffu, m, off));
    float ssum = expf(v0 - m) + ((lane < 8) ? expf(v1 - m) : 0.f);
    #pragma unroll
    for (int off = 16; off > 0; off >>= 1)
        ssum += __shfl_xor_sync(0xffffffffu, ssum, off);
    float lse = m + logf(ssum);
    out[lane * N_NODES + node] = v0 - lse;
    if (lane < 8) out[(32 + lane) * N_NODES + node] = v1 - lse;
}

// ---------------- launcher ----------------
extern "C" void kernel_launch(void* const* d_in, const int* in_sizes, int n_in,
                              void* d_out, int out_size) {
    const float* x   = (const float*)d_in[0];
    const int*   ei  = (const int*)d_in[1];     // int32 (JAX downcasts int64)
    const float* Wl1 = (const float*)d_in[2];
    const float* bl1 = (const float*)d_in[3];
    const float* Wr1 = (const float*)d_in[4];
    const float* Wl2 = (const float*)d_in[5];
    const float* bl2 = (const float*)d_in[6];
    const float* Wr2 = (const float*)d_in[7];
    float* out = (float*)d_out;

    cudaFuncSetAttribute(k_gemm12, cudaFuncAttributeMaxDynamicSharedMemorySize,
                         G12_SMEM_FLOATS * (int)sizeof(float));

    k_zero_cnt<<<(N_NODES + 255) / 256, 256>>>();
    k_degree<<<(N_EDGES / 4 + 255) / 256, 256>>>(ei);
    k_scan_part<<<NB_SCAN, 1024>>>();
    k_scan_add<<<(N_NODES + 255) / 256, 256>>>();
    k_fill<<<(N_EDGES / 4 + 255) / 256, 256>>>(ei);
    k_gemm12<<<(N_NODES + 63) / 64, 256, G12_SMEM_FLOATS * sizeof(float)>>>(
        x, Wl1, bl1, Wr1, Wl2, Wr2);
    k_agglout<<<(N_NODES + 7) / 8, 256>>>(bl2, out);
}